// round 9
// baseline (speedup 1.0000x reference)
#include <cuda_runtime.h>
#include <cuda_bf16.h>

// ---------------------------------------------------------------------------
// out[m] = sum_n I_n * exp(-0.5 * (x_m)^T A_n x_m - 2 b_n.x_m + c_n)
// Folded: t = K*(x^T A x - 2 b.x + c) + log2(I),  K = -0.5*log2(e)
//         out[m] = sum_n exp2(t)
// 10 coefficients per gaussian, pre-splatted as f32x2 pairs (80 B/gaussian).
//
// R9: 6 points/thread (3 f32x2 chains) @ 3 CTAs/SM (85 regs) -> 6 warps/SMSP
//     for stall coverage of the dual FMA+MUFU pipe load.
// ---------------------------------------------------------------------------

#define NG_MAX 8192
__device__ __align__(16) float g_coef[NG_MAX * 20];

#define GCHUNK 64            // gaussians per tile (5 KB per smem buffer)
#define NCH 3                // f32x2 chains per thread (6 points)
#define PTS_PER_TILE 1536    // 256 threads * 6 points
#define CTAS_PER_SM 3

// ---- f32x2 packed helpers --------------------------------------------------
__device__ __forceinline__ unsigned long long fma2(unsigned long long a,
                                                   unsigned long long b,
                                                   unsigned long long c) {
    unsigned long long d;
    asm("fma.rn.f32x2 %0, %1, %2, %3;" : "=l"(d) : "l"(a), "l"(b), "l"(c));
    return d;
}
__device__ __forceinline__ unsigned long long add2(unsigned long long a,
                                                   unsigned long long b) {
    unsigned long long d;
    asm("add.rn.f32x2 %0, %1, %2;" : "=l"(d) : "l"(a), "l"(b));
    return d;
}
__device__ __forceinline__ unsigned long long mul2(unsigned long long a,
                                                   unsigned long long b) {
    unsigned long long d;
    asm("mul.rn.f32x2 %0, %1, %2;" : "=l"(d) : "l"(a), "l"(b));
    return d;
}
__device__ __forceinline__ unsigned long long pk2(float lo, float hi) {
    unsigned long long r;
    asm("mov.b64 %0, {%1, %2};" : "=l"(r) : "f"(lo), "f"(hi));
    return r;
}
__device__ __forceinline__ void upk2(unsigned long long v, float& lo, float& hi) {
    asm("mov.b64 {%0, %1}, %2;" : "=f"(lo), "=f"(hi) : "l"(v));
}
__device__ __forceinline__ float ex2(float x) {
    float y;
    asm("ex2.approx.ftz.f32 %0, %1;" : "=f"(y) : "f"(x));
    return y;
}
__device__ __forceinline__ unsigned int smem_u32(const void* p) {
    unsigned int a;
    asm("{ .reg .u64 t; cvta.to.shared.u64 t, %1; cvt.u32.u64 %0, t; }"
        : "=r"(a) : "l"(p));
    return a;
}
__device__ __forceinline__ void cp_async16(unsigned int dst, const void* src) {
    asm volatile("cp.async.cg.shared.global [%0], [%1], 16;"
                 :: "r"(dst), "l"(src));
}
__device__ __forceinline__ void cp_commit() {
    asm volatile("cp.async.commit_group;");
}
__device__ __forceinline__ void cp_wait1() {
    asm volatile("cp.async.wait_group 1;");
}
__device__ __forceinline__ void cp_wait0() {
    asm volatile("cp.async.wait_group 0;");
}

// ---------------------------------------------------------------------------
// Prep: coefficients; pads [n, n_pad) with cf = -inf (exp2 -> 0).
// ---------------------------------------------------------------------------
__global__ void prep_kernel(const float* __restrict__ positions,
                            const float* __restrict__ scales,
                            const float* __restrict__ rotations,
                            const float* __restrict__ intensities,
                            int n, int n_pad) {
    int g = blockIdx.x * blockDim.x + threadIdx.x;
    if (g >= n_pad || g >= NG_MAX) return;

    float v[10];
    if (g >= n) {
#pragma unroll
        for (int k = 0; k < 9; k++) v[k] = 0.0f;
        v[9] = -__int_as_float(0x7f800000);  // -inf
    } else {
        float qw = rotations[4 * g + 0];
        float qx = rotations[4 * g + 1];
        float qy = rotations[4 * g + 2];
        float qz = rotations[4 * g + 3];
        float nrm = sqrtf(qw * qw + qx * qx + qy * qy + qz * qz);
        float inv = 1.0f / (nrm + 1e-8f);
        qw *= inv; qx *= inv; qy *= inv; qz *= inv;

        float r00 = 1.0f - 2.0f * (qy * qy + qz * qz);
        float r01 = 2.0f * (qx * qy - qz * qw);
        float r02 = 2.0f * (qx * qz + qy * qw);
        float r10 = 2.0f * (qx * qy + qz * qw);
        float r11 = 1.0f - 2.0f * (qx * qx + qz * qz);
        float r12 = 2.0f * (qy * qz - qx * qw);
        float r20 = 2.0f * (qx * qz - qy * qw);
        float r21 = 2.0f * (qy * qz + qx * qw);
        float r22 = 1.0f - 2.0f * (qx * qx + qy * qy);

        float s0 = fabsf(scales[3 * g + 0]) + 1e-6f;
        float s1 = fabsf(scales[3 * g + 1]) + 1e-6f;
        float s2 = fabsf(scales[3 * g + 2]) + 1e-6f;
        float i0 = 1.0f / (s0 * s0);
        float i1 = 1.0f / (s1 * s1);
        float i2 = 1.0f / (s2 * s2);

        float a00 = r00 * r00 * i0 + r01 * r01 * i1 + r02 * r02 * i2;
        float a01 = r00 * r10 * i0 + r01 * r11 * i1 + r02 * r12 * i2;
        float a02 = r00 * r20 * i0 + r01 * r21 * i1 + r02 * r22 * i2;
        float a11 = r10 * r10 * i0 + r11 * r11 * i1 + r12 * r12 * i2;
        float a12 = r10 * r20 * i0 + r11 * r21 * i1 + r12 * r22 * i2;
        float a22 = r20 * r20 * i0 + r21 * r21 * i1 + r22 * r22 * i2;

        float px = positions[3 * g + 0];
        float py = positions[3 * g + 1];
        float pz = positions[3 * g + 2];
        float bx = a00 * px + a01 * py + a02 * pz;
        float by = a01 * px + a11 * py + a12 * pz;
        float bz = a02 * px + a12 * py + a22 * pz;
        float c  = bx * px + by * py + bz * pz;

        const float K = -0.72134752044448169f;  // -0.5 * log2(e)
        v[0] = K * a00;
        v[1] = K * a11;
        v[2] = K * a22;
        v[3] = 2.0f * K * a01;
        v[4] = 2.0f * K * a02;
        v[5] = 2.0f * K * a12;
        v[6] = -2.0f * K * bx;
        v[7] = -2.0f * K * by;
        v[8] = -2.0f * K * bz;
        v[9] = K * c + log2f(intensities[g]);
    }

#pragma unroll
    for (int k = 0; k < 10; k++) {
        g_coef[g * 20 + 2 * k + 0] = v[k];
        g_coef[g * 20 + 2 * k + 1] = v[k];
    }
}

// ---------------------------------------------------------------------------
// Persistent main kernel; 6 points per thread as 3 f32x2 chains.
// ---------------------------------------------------------------------------
__global__ void __launch_bounds__(256, CTAS_PER_SM)
gauss_kernel(const float* __restrict__ pts, float* __restrict__ out,
             int M, int gc_tiles, int pb_tiles, int n_ctas) {
    __shared__ __align__(16) float sm[2][GCHUNK * 20];

    const int tid = threadIdx.x;
    const int cta = blockIdx.x;
    const int tiles = gc_tiles * pb_tiles;

    const int t0 = (int)(((long long)cta * tiles) / n_ctas);
    const int t1 = (int)(((long long)(cta + 1) * tiles) / n_ctas);
    if (t0 >= t1) return;

    const unsigned int sbase0 = smem_u32(&sm[0][0]);
    const unsigned int sbase1 = smem_u32(&sm[1][0]);

    auto stage = [&](int t, unsigned int sbase) {
        int gc = t % gc_tiles;
        const char* src = (const char*)g_coef + (size_t)gc * GCHUNK * 80;
#pragma unroll
        for (int i = tid; i < GCHUNK * 5; i += 256) {
            cp_async16(sbase + i * 16, src + i * 16);
        }
        cp_commit();
    };

    stage(t0, sbase0);

    // NCH f32x2 chains (2 points each): coords, products, accumulators
    unsigned long long X[NCH], Y[NCH], Z[NCH];
    unsigned long long XX[NCH], YY[NCH], ZZ[NCH];
    unsigned long long XY[NCH], XZ[NCH], YZ[NCH];
    unsigned long long ACC[NCH];
    int cur_pb = -1;
    int p0 = 0;

    for (int t = t0; t < t1; ++t) {
        const int buf = (t - t0) & 1;

        if (t + 1 < t1) {
            stage(t + 1, buf ? sbase0 : sbase1);
            cp_wait1();
        } else {
            cp_wait0();
        }
        __syncthreads();

        const int pb = t / gc_tiles;
        if (pb != cur_pb) {
            if (cur_pb >= 0) {
#pragma unroll
                for (int j = 0; j < NCH; j++) {
                    float a0, a1;
                    upk2(ACC[j], a0, a1);
                    int p = p0 + j * 512;
                    if (p < M)       atomicAdd(out + p, a0);
                    if (p + 256 < M) atomicAdd(out + p + 256, a1);
                }
            }
            cur_pb = pb;
            p0 = pb * PTS_PER_TILE + tid;
#pragma unroll
            for (int j = 0; j < NCH; j++) {
                int pa = p0 + j * 512;
                int pb2 = pa + 256;
                bool oka = (pa < M), okb = (pb2 < M);
                float xa = oka ? pts[3 * pa + 0] : 0.0f;
                float ya = oka ? pts[3 * pa + 1] : 0.0f;
                float za = oka ? pts[3 * pa + 2] : 0.0f;
                float xb = okb ? pts[3 * pb2 + 0] : 0.0f;
                float yb = okb ? pts[3 * pb2 + 1] : 0.0f;
                float zb = okb ? pts[3 * pb2 + 2] : 0.0f;
                X[j] = pk2(xa, xb);
                Y[j] = pk2(ya, yb);
                Z[j] = pk2(za, zb);
                XX[j] = mul2(X[j], X[j]);
                YY[j] = mul2(Y[j], Y[j]);
                ZZ[j] = mul2(Z[j], Z[j]);
                XY[j] = mul2(X[j], Y[j]);
                XZ[j] = mul2(X[j], Z[j]);
                YZ[j] = mul2(Y[j], Z[j]);
                ACC[j] = 0ull;
            }
        }

        const ulonglong2* recs =
            (const ulonglong2*)(buf ? &sm[1][0] : &sm[0][0]);
#pragma unroll 2
        for (int g = 0; g < GCHUNK; ++g) {
            ulonglong2 q0 = recs[g * 5 + 0];  // Ka00 | Ka11
            ulonglong2 q1 = recs[g * 5 + 1];  // Ka22 | 2Ka01
            ulonglong2 q2 = recs[g * 5 + 2];  // 2Ka02 | 2Ka12
            ulonglong2 q3 = recs[g * 5 + 3];  // bx | by
            ulonglong2 q4 = recs[g * 5 + 4];  // bz | cf

            unsigned long long T[NCH];
#pragma unroll
            for (int j = 0; j < NCH; j++) T[j] = fma2(q0.x, XX[j], q4.y);
#pragma unroll
            for (int j = 0; j < NCH; j++) T[j] = fma2(q0.y, YY[j], T[j]);
#pragma unroll
            for (int j = 0; j < NCH; j++) T[j] = fma2(q1.x, ZZ[j], T[j]);
#pragma unroll
            for (int j = 0; j < NCH; j++) T[j] = fma2(q1.y, XY[j], T[j]);
#pragma unroll
            for (int j = 0; j < NCH; j++) T[j] = fma2(q2.x, XZ[j], T[j]);
#pragma unroll
            for (int j = 0; j < NCH; j++) T[j] = fma2(q2.y, YZ[j], T[j]);
#pragma unroll
            for (int j = 0; j < NCH; j++) T[j] = fma2(q3.x, X[j], T[j]);
#pragma unroll
            for (int j = 0; j < NCH; j++) T[j] = fma2(q3.y, Y[j], T[j]);
#pragma unroll
            for (int j = 0; j < NCH; j++) T[j] = fma2(q4.x, Z[j], T[j]);

#pragma unroll
            for (int j = 0; j < NCH; j++) {
                float f0, f1;
                upk2(T[j], f0, f1);
                float e0 = ex2(f0), e1 = ex2(f1);
                ACC[j] = add2(ACC[j], pk2(e0, e1));
            }
        }
        __syncthreads();
    }

    if (cur_pb >= 0) {
#pragma unroll
        for (int j = 0; j < NCH; j++) {
            float a0, a1;
            upk2(ACC[j], a0, a1);
            int p = p0 + j * 512;
            if (p < M)       atomicAdd(out + p, a0);
            if (p + 256 < M) atomicAdd(out + p + 256, a1);
        }
    }
}

// ---------------------------------------------------------------------------
extern "C" void kernel_launch(void* const* d_in, const int* in_sizes, int n_in,
                              void* d_out, int out_size) {
    const float* sample_points = (const float*)d_in[0];
    const float* positions     = (const float*)d_in[1];
    const float* scales        = (const float*)d_in[2];
    const float* rotations     = (const float*)d_in[3];
    const float* intensities   = (const float*)d_in[4];
    float* out = (float*)d_out;

    int M = in_sizes[0] / 3;
    int n = in_sizes[4];
    int n_pad = ((n + GCHUNK - 1) / GCHUNK) * GCHUNK;
    if (n_pad > NG_MAX) n_pad = NG_MAX;

    cudaMemsetAsync(out, 0, (size_t)out_size * sizeof(float));

    prep_kernel<<<(n_pad + 255) / 256, 256>>>(positions, scales, rotations,
                                              intensities, n, n_pad);

    int sms = 148;
    cudaDeviceGetAttribute(&sms, cudaDevAttrMultiProcessorCount, 0);
    int n_ctas = sms * CTAS_PER_SM;

    int pb_tiles = (M + PTS_PER_TILE - 1) / PTS_PER_TILE;   // 43
    int gc_tiles = n_pad / GCHUNK;                           // 64
    int tiles = pb_tiles * gc_tiles;
    if (n_ctas > tiles) n_ctas = tiles;

    gauss_kernel<<<n_ctas, 256>>>(sample_points, out, M, gc_tiles, pb_tiles,
                                  n_ctas);
}

// round 11
// speedup vs baseline: 1.4401x; 1.4401x over previous
#include <cuda_runtime.h>
#include <cstdint>

// ---------------------------------------------------------------------------
// out[m] = sum_n I_n * exp(-0.5 (x-mu)^T A (x-mu))
//        = sum_n exp2( monomials(x_m) . coef_n )       (everything folded)
// coef order k=0..7 : x2,y2,z2,xy | xz,yz,x,y   -> handled by mma.sync tf32
// k=8 (z), k=9 (1=cf) -> scalar f32 tail folded into the MMA C operand.
//
// R11: legacy mma.sync.m16n8k8 3xTF32 (hi*hi + hi*lo + lo*hi), MUFU-bound
//      epilogue (ex2). tcgen05 is unavailable (harness lowers via compute_103).
// ---------------------------------------------------------------------------

#define NG_MAX 8192
#define CHUNK_FLOATS 144   // per 8-gaussian chunk: 8*16 mma floats + 16 scalar
#define SPLIT_G 256
#define NCHUNK 32          // chunks per split
#define SPLIT_FLOATS (NCHUNK * CHUNK_FLOATS)   // 4608 floats = 18432 B
#define PTB 256            // points per CTA ticket
#define CTAS_PER_SM 3

__device__ __align__(16) float g_b[(NG_MAX / 8) * CHUNK_FLOATS];

// ---- helpers ---------------------------------------------------------------
__device__ __forceinline__ float ex2(float x) {
    float y;
    asm("ex2.approx.ftz.f32 %0, %1;" : "=f"(y) : "f"(x));
    return y;
}
__device__ __forceinline__ uint32_t tf32_of(float v) {
    uint32_t r;
    asm("cvt.rna.tf32.f32 %0, %1;" : "=r"(r) : "f"(v));
    return r;
}
__device__ __forceinline__ void tf32split(float v, uint32_t& hi, uint32_t& lo) {
    hi = tf32_of(v);
    lo = tf32_of(v - __uint_as_float(hi));
}
__device__ __forceinline__ uint32_t smem_u32(const void* p) {
    uint32_t a;
    asm("{ .reg .u64 t; cvta.to.shared.u64 t, %1; cvt.u32.u64 %0, t; }"
        : "=r"(a) : "l"(p));
    return a;
}
__device__ __forceinline__ void cp_async16(uint32_t dst, const void* src) {
    asm volatile("cp.async.cg.shared.global [%0], [%1], 16;"
                 :: "r"(dst), "l"(src));
}
__device__ __forceinline__ void cp_commit() {
    asm volatile("cp.async.commit_group;");
}
__device__ __forceinline__ void cp_wait1() {
    asm volatile("cp.async.wait_group 1;");
}
__device__ __forceinline__ void cp_wait0() {
    asm volatile("cp.async.wait_group 0;");
}

// D = A(tf32) * B(tf32) + C   (m16n8k8, row.col)
__device__ __forceinline__ void mma8(float d[4], const uint32_t a[4],
                                     uint32_t b0, uint32_t b1,
                                     float c0, float c1, float c2, float c3) {
    asm("mma.sync.aligned.m16n8k8.row.col.f32.tf32.tf32.f32 "
        "{%0,%1,%2,%3}, {%4,%5,%6,%7}, {%8,%9}, {%10,%11,%12,%13};"
        : "=f"(d[0]), "=f"(d[1]), "=f"(d[2]), "=f"(d[3])
        : "r"(a[0]), "r"(a[1]), "r"(a[2]), "r"(a[3]),
          "r"(b0), "r"(b1),
          "f"(c0), "f"(c1), "f"(c2), "f"(c3));
}

// ---------------------------------------------------------------------------
// Prep: 10 coefficients per gaussian, packed for per-lane fragment loads.
// chunk c = g/8, slot i = g%8, chunk base = c*144 floats:
//   mma region  [(i*4 + j)*4 .. +4) = (hi[v_j], hi[v_{j+4}], lo[v_j], lo[v_{j+4}])
//   scalar      [128 + i*2]         = (v8 (z coef), v9 (cf))
// ---------------------------------------------------------------------------
__global__ void prep_kernel(const float* __restrict__ positions,
                            const float* __restrict__ scales,
                            const float* __restrict__ rotations,
                            const float* __restrict__ intensities,
                            int n, int n_pad) {
    int g = blockIdx.x * blockDim.x + threadIdx.x;
    if (g >= n_pad || g >= NG_MAX) return;

    float v[10];
    if (g >= n) {
#pragma unroll
        for (int k = 0; k < 9; k++) v[k] = 0.0f;
        v[9] = -1000.0f;  // exp2 -> 0
    } else {
        float qw = rotations[4 * g + 0];
        float qx = rotations[4 * g + 1];
        float qy = rotations[4 * g + 2];
        float qz = rotations[4 * g + 3];
        float nrm = sqrtf(qw * qw + qx * qx + qy * qy + qz * qz);
        float inv = 1.0f / (nrm + 1e-8f);
        qw *= inv; qx *= inv; qy *= inv; qz *= inv;

        float r00 = 1.0f - 2.0f * (qy * qy + qz * qz);
        float r01 = 2.0f * (qx * qy - qz * qw);
        float r02 = 2.0f * (qx * qz + qy * qw);
        float r10 = 2.0f * (qx * qy + qz * qw);
        float r11 = 1.0f - 2.0f * (qx * qx + qz * qz);
        float r12 = 2.0f * (qy * qz - qx * qw);
        float r20 = 2.0f * (qx * qz - qy * qw);
        float r21 = 2.0f * (qy * qz + qx * qw);
        float r22 = 1.0f - 2.0f * (qx * qx + qy * qy);

        float s0 = fabsf(scales[3 * g + 0]) + 1e-6f;
        float s1 = fabsf(scales[3 * g + 1]) + 1e-6f;
        float s2 = fabsf(scales[3 * g + 2]) + 1e-6f;
        float i0 = 1.0f / (s0 * s0);
        float i1 = 1.0f / (s1 * s1);
        float i2 = 1.0f / (s2 * s2);

        float a00 = r00 * r00 * i0 + r01 * r01 * i1 + r02 * r02 * i2;
        float a01 = r00 * r10 * i0 + r01 * r11 * i1 + r02 * r12 * i2;
        float a02 = r00 * r20 * i0 + r01 * r21 * i1 + r02 * r22 * i2;
        float a11 = r10 * r10 * i0 + r11 * r11 * i1 + r12 * r12 * i2;
        float a12 = r10 * r20 * i0 + r11 * r21 * i1 + r12 * r22 * i2;
        float a22 = r20 * r20 * i0 + r21 * r21 * i1 + r22 * r22 * i2;

        float px = positions[3 * g + 0];
        float py = positions[3 * g + 1];
        float pz = positions[3 * g + 2];
        float bx = a00 * px + a01 * py + a02 * pz;
        float by = a01 * px + a11 * py + a12 * pz;
        float bz = a02 * px + a12 * py + a22 * pz;
        float c  = bx * px + by * py + bz * pz;

        const float K = -0.72134752044448169f;  // -0.5 * log2(e)
        v[0] = K * a00;           // x^2
        v[1] = K * a11;           // y^2
        v[2] = K * a22;           // z^2
        v[3] = 2.0f * K * a01;    // xy
        v[4] = 2.0f * K * a02;    // xz
        v[5] = 2.0f * K * a12;    // yz
        v[6] = -2.0f * K * bx;    // x
        v[7] = -2.0f * K * by;    // y
        v[8] = -2.0f * K * bz;    // z   (scalar tail)
        v[9] = K * c + log2f(fmaxf(intensities[g], 1e-30f));  // const (scalar)
    }

    float* base = g_b + (size_t)(g >> 3) * CHUNK_FLOATS;
    int i = g & 7;
#pragma unroll
    for (int j = 0; j < 4; j++) {
        uint32_t h0, l0, h1, l1;
        tf32split(v[j], h0, l0);
        tf32split(v[j + 4], h1, l1);
        float4 w;
        w.x = __uint_as_float(h0);
        w.y = __uint_as_float(h1);
        w.z = __uint_as_float(l0);
        w.w = __uint_as_float(l1);
        *(float4*)(base + (i * 4 + j) * 4) = w;
    }
    base[128 + i * 2 + 0] = v[8];
    base[128 + i * 2 + 1] = v[9];
}

// ---------------------------------------------------------------------------
// Main: persistent CTAs; ticket = (256-pt block) x (256-gaussian split).
// Per warp: 32 points as two m16n8 MMA tiles; loop 32 chunks of 8 gaussians.
// ---------------------------------------------------------------------------
__global__ void __launch_bounds__(256, CTAS_PER_SM)
gauss_kernel(const float* __restrict__ pts, float* __restrict__ out,
             int M, int pt_blocks, int gsplits, int n_ctas) {
    extern __shared__ __align__(16) float smb[];  // 2 * SPLIT_FLOATS

    const int tid  = threadIdx.x;
    const int wid  = tid >> 5;
    const int lane = tid & 31;
    const int j    = lane & 3;      // threadID_in_group
    const int grp  = lane >> 2;     // groupID (B col / D row / A row)

    const long long tickets = (long long)pt_blocks * gsplits;
    const int t0 = (int)(((long long)blockIdx.x * tickets) / n_ctas);
    const int t1 = (int)(((long long)(blockIdx.x + 1) * tickets) / n_ctas);
    if (t0 >= t1) return;

    const uint32_t sb0 = smem_u32(smb);
    const uint32_t sb1 = sb0 + SPLIT_FLOATS * 4;

    auto stage = [&](int tk, uint32_t dst) {
        const int gs = tk % gsplits;
        const char* src = (const char*)(g_b + (size_t)gs * SPLIT_FLOATS);
#pragma unroll
        for (int i = tid; i < SPLIT_FLOATS / 4; i += 256)
            cp_async16(dst + (uint32_t)i * 16u, src + (size_t)i * 16);
        cp_commit();
    };

    stage(t0, sb0);

    for (int tk = t0; tk < t1; ++tk) {
        const int buf = (tk - t0) & 1;

        if (tk + 1 < t1) {
            stage(tk + 1, buf ? sb0 : sb1);
            cp_wait1();
        } else {
            cp_wait0();
        }
        __syncthreads();

        // ---- build A fragments for two 16-row tiles (32 points per warp)
        const int ptb   = tk / gsplits;
        const int pbase = ptb * PTB + wid * 32 + grp;
        uint32_t ahi[2][4], alo[2][4];
        float zr[2][2];
#pragma unroll
        for (int tI = 0; tI < 2; tI++) {
#pragma unroll
            for (int rI = 0; rI < 2; rI++) {
                int p = pbase + tI * 16 + rI * 8;
                float x = 0.f, y = 0.f, z = 0.f;
                if (p < M) { x = pts[3 * p]; y = pts[3 * p + 1]; z = pts[3 * p + 2]; }
                // monomial k=j and k=j+4 for this point
                float m0 = (j == 0) ? x * x : (j == 1) ? y * y
                         : (j == 2) ? z * z : x * y;
                float m1 = (j == 0) ? x * z : (j == 1) ? y * z
                         : (j == 2) ? x : y;
                tf32split(m0, ahi[tI][0 + rI], alo[tI][0 + rI]);  // a0/a1: col j
                tf32split(m1, ahi[tI][2 + rI], alo[tI][2 + rI]);  // a2/a3: col j+4
                zr[tI][rI] = z;
            }
        }

        float acc[2][2] = {{0.f, 0.f}, {0.f, 0.f}};
        const float* sbuf = smb + (buf ? SPLIT_FLOATS : 0);

#pragma unroll 2
        for (int c = 0; c < NCHUNK; ++c) {
            const float* cb = sbuf + c * CHUNK_FLOATS;
            // B fragment: (hi_j, hi_j4, lo_j, lo_j4) for gaussian n=grp
            float4 bv = *(const float4*)(cb + (grp * 4 + j) * 4);
            // scalar tail for D cols 2j, 2j+1: (bz0, cf0, bz1, cf1)
            float4 sc = *(const float4*)(cb + 128 + j * 4);
            const uint32_t bh0 = __float_as_uint(bv.x);
            const uint32_t bh1 = __float_as_uint(bv.y);
            const uint32_t bl0 = __float_as_uint(bv.z);
            const uint32_t bl1 = __float_as_uint(bv.w);

#pragma unroll
            for (int tI = 0; tI < 2; tI++) {
                float d[4];
                float c0 = fmaf(sc.x, zr[tI][0], sc.y);
                float c1 = fmaf(sc.z, zr[tI][0], sc.w);
                float c2 = fmaf(sc.x, zr[tI][1], sc.y);
                float c3 = fmaf(sc.z, zr[tI][1], sc.w);
                mma8(d, ahi[tI], bh0, bh1, c0, c1, c2, c3);      // hi*hi + tail
                mma8(d, ahi[tI], bl0, bl1, d[0], d[1], d[2], d[3]);  // hi*lo
                mma8(d, alo[tI], bh0, bh1, d[0], d[1], d[2], d[3]);  // lo*hi
                acc[tI][0] += ex2(d[0]) + ex2(d[1]);
                acc[tI][1] += ex2(d[2]) + ex2(d[3]);
            }
        }
        __syncthreads();

        // ---- reduce each row-sum over the 4 lanes of the quad, then atomic
#pragma unroll
        for (int tI = 0; tI < 2; tI++) {
#pragma unroll
            for (int rI = 0; rI < 2; rI++) {
                float v = acc[tI][rI];
                v += __shfl_xor_sync(0xffffffffu, v, 1);
                v += __shfl_xor_sync(0xffffffffu, v, 2);
                int p = pbase + tI * 16 + rI * 8;
                if (j == 0 && p < M) atomicAdd(out + p, v);
            }
        }
    }
}

// ---------------------------------------------------------------------------
extern "C" void kernel_launch(void* const* d_in, const int* in_sizes, int n_in,
                              void* d_out, int out_size) {
    const float* sample_points = (const float*)d_in[0];
    const float* positions     = (const float*)d_in[1];
    const float* scales        = (const float*)d_in[2];
    const float* rotations     = (const float*)d_in[3];
    const float* intensities   = (const float*)d_in[4];
    float* out = (float*)d_out;

    int M = in_sizes[0] / 3;
    int n = in_sizes[4];
    int n_pad = ((n + SPLIT_G - 1) / SPLIT_G) * SPLIT_G;
    if (n_pad > NG_MAX) n_pad = NG_MAX;

    cudaMemsetAsync(out, 0, (size_t)out_size * sizeof(float));

    prep_kernel<<<(n_pad + 127) / 128, 128>>>(positions, scales, rotations,
                                              intensities, n, n_pad);

    int sms = 148;
    cudaDeviceGetAttribute(&sms, cudaDevAttrMultiProcessorCount, 0);

    int pt_blocks = (M + PTB - 1) / PTB;      // 256
    int gsplits   = n_pad / SPLIT_G;          // 16
    long long tickets = (long long)pt_blocks * gsplits;  // 4096

    int n_ctas = sms * CTAS_PER_SM;
    if ((long long)n_ctas > tickets) n_ctas = (int)tickets;

    gauss_kernel<<<n_ctas, 256, 2 * SPLIT_FLOATS * 4>>>(
        sample_points, out, M, pt_blocks, gsplits, n_ctas);
}